// round 2
// baseline (speedup 1.0000x reference)
#include <cuda_runtime.h>
#include <math.h>

#define N_ATOMS 20000
#define N_EDGES 320000
#define FDIM    64

typedef unsigned long long ull;

// ---------------- device scratch (static, no allocations) ----------------
__device__ float g_comps[N_ATOMS * 9 * FDIM];   // Y in compact comp form [n][c][f]
__device__ float g_msg  [N_ATOMS * 9 * FDIM];   // reduced messages  [n][c][f]
__device__ float g_rfv  [N_EDGES * 192];        // edge radial feats [e][k][f]
__device__ int   g_cnt [N_ATOMS];
__device__ int   g_off [N_ATOMS + 1];
__device__ int   g_cur [N_ATOMS];
__device__ int   g_slot[N_EDGES];

// ---------------- helpers ----------------
__device__ __forceinline__ ull pack2(float x, float y) {
    ull r; asm("mov.b64 %0, {%1,%2};" : "=l"(r) : "f"(x), "f"(y)); return r;
}
__device__ __forceinline__ void unpack2(ull v, float& x, float& y) {
    asm("mov.b64 {%0,%1}, %2;" : "=f"(x), "=f"(y) : "l"(v));
}
__device__ __forceinline__ ull fma2(ull a, ull b, ull c) {
    ull d; asm("fma.rn.f32x2 %0, %1, %2, %3;" : "=l"(d) : "l"(a), "l"(b), "l"(c)); return d;
}
__device__ __forceinline__ float siluf(float x) {
    return __fdividef(x, 1.0f + __expf(-x));
}
// comps order: 0:i  1:a01 2:a02 3:a12  4:s00 5:s01 6:s02 7:s11 8:s12
__device__ __forceinline__ void recon(const float* c, float* T) {
    T[0] = c[0] + c[4];  T[1] = c[1] + c[5];  T[2] = c[2] + c[6];
    T[3] = c[5] - c[1];  T[4] = c[0] + c[7];  T[5] = c[3] + c[8];
    T[6] = c[6] - c[2];  T[7] = c[8] - c[3];  T[8] = c[0] - c[4] - c[7];
}
__device__ __forceinline__ void madd3(const float* A, const float* B, float* P) {
#pragma unroll
    for (int i = 0; i < 3; i++)
#pragma unroll
        for (int j = 0; j < 3; j++) {
            float s = P[i * 3 + j];
#pragma unroll
            for (int k = 0; k < 3; k++) s += A[i * 3 + k] * B[k * 3 + j];
            P[i * 3 + j] = s;
        }
}
__device__ __forceinline__ void decomp(const float* P, float* c) {
    float dm = (P[0] + P[4] + P[8]) * (1.0f / 3.0f);
    c[0] = dm;
    c[1] = 0.5f * (P[1] - P[3]);
    c[2] = 0.5f * (P[2] - P[6]);
    c[3] = 0.5f * (P[5] - P[7]);
    c[4] = P[0] - dm;
    c[5] = 0.5f * (P[1] + P[3]);
    c[6] = 0.5f * (P[2] + P[6]);
    c[7] = P[4] - dm;
    c[8] = 0.5f * (P[5] + P[7]);
}

// ============== K1: normalize X, decompose, 3 tensor-linears -> g_comps ==============
__global__ void k_node_pre(const float* __restrict__ X, const float* __restrict__ Wt) {
    extern __shared__ float sm[];
    float* sWT = sm;             // 12288: [m][f][g] transposed
    float* sX  = sm + 12288;     // 576
    float* sC  = sX + 576;       // 576: comps [c][f]
    int t = threadIdx.x;
    for (int i = t; i < 12288; i += blockDim.x) {
        int m = i >> 12, r = i & 4095, f = r >> 6, g = r & 63;
        sWT[i] = Wt[m * 4096 + g * 64 + f];
    }
    __syncthreads();
    for (int n = blockIdx.x; n < N_ATOMS; n += gridDim.x) {
        for (int i = t; i < 576; i += blockDim.x) sX[i] = X[n * 576 + i];
        __syncthreads();
        if (t < 64) {
            int f = t;
            const float* x = sX + f * 9;
            float tn = 0.f, xv[9];
#pragma unroll
            for (int j = 0; j < 9; j++) tn += x[j] * x[j];
            float inv = 1.f / (tn + 1.f);
#pragma unroll
            for (int j = 0; j < 9; j++) xv[j] = x[j] * inv;
            float c[9]; decomp(xv, c);
#pragma unroll
            for (int j = 0; j < 9; j++) sC[j * 64 + f] = c[j];
        }
        __syncthreads();
        for (int i = t; i < 576; i += blockDim.x) {
            int c = i >> 6, g = i & 63;
            int m = (c == 0) ? 0 : (c < 4) ? 1 : 2;
            const float* wr = sWT + m * 4096;
            const float* in = sC + c * 64;
            float acc = 0.f;
#pragma unroll 8
            for (int f = 0; f < 64; f++) acc += wr[f * 64 + g] * in[f];
            g_comps[n * 576 + i] = acc;
        }
        __syncthreads();
    }
}

// ============== CSR build ==============
__global__ void k_zero() {
    int i = blockIdx.x * blockDim.x + threadIdx.x;
    if (i < N_ATOMS) g_cnt[i] = 0;
}
__global__ void k_hist(const int* __restrict__ pr) {
    int e = blockIdx.x * blockDim.x + threadIdx.x;
    if (e < N_EDGES) atomicAdd(&g_cnt[pr[e]], 1);   // dst = row 0
}
__global__ void k_scan() {                          // 1 block, 1024 threads
    __shared__ int s[1024];
    const int CH = 20;
    int t = threadIdx.x;
    int base = t * CH;
    int local[CH];
    int sum = 0;
#pragma unroll
    for (int i = 0; i < CH; i++) {
        int idx = base + i;
        int v = (idx < N_ATOMS) ? g_cnt[idx] : 0;
        local[i] = sum; sum += v;
    }
    s[t] = sum; __syncthreads();
    for (int d = 1; d < 1024; d <<= 1) {
        int v = (t >= d) ? s[t - d] : 0;
        __syncthreads();
        s[t] += v;
        __syncthreads();
    }
    int pre = (t == 0) ? 0 : s[t - 1];
#pragma unroll
    for (int i = 0; i < CH; i++) {
        int idx = base + i;
        if (idx < N_ATOMS) { int o = pre + local[i]; g_off[idx] = o; g_cur[idx] = o; }
    }
    if (t == 1023) g_off[N_ATOMS] = s[1023];
}
__global__ void k_scatter(const int* __restrict__ pr) {
    int e = blockIdx.x * blockDim.x + threadIdx.x;
    if (e < N_EDGES) {
        int pos = atomicAdd(&g_cur[pr[e]], 1);
        g_slot[pos] = e;
    }
}

// ============== K2: edge MLP (lane-per-edge, f32x2, smem-broadcast weights) ==============
__global__ void __launch_bounds__(256)
k_edge_mlp(const float* __restrict__ rf, const float* __restrict__ dij,
           const float* __restrict__ W0, const float* __restrict__ b0,
           const float* __restrict__ W1, const float* __restrict__ b1,
           const float* __restrict__ W2, const float* __restrict__ b2) {
    extern __shared__ ull smu[];
    ull* sW0p = smu;                 // [k<32][p<32]
    ull* sB0p = sW0p + 1024;         // 32
    ull* sW1p = sB0p + 32;           // [k<64][p<64]
    ull* sB1p = sW1p + 4096;         // 64
    ull* sW2p = sB1p + 64;           // [k<128][c<3][p<32] output-permuted
    ull* sB2p = sW2p + 12288;        // 96
    float* sStage = (float*)(sB2p + 96);   // 8 warps * 2080 floats
    int t = threadIdx.x;

    for (int i = t; i < 1024; i += 256) {
        int k = i >> 5, p = i & 31;
        sW0p[i] = pack2(W0[(2 * p) * 32 + k], W0[(2 * p + 1) * 32 + k]);
    }
    for (int i = t; i < 4096; i += 256) {
        int k = i >> 6, p = i & 63;
        sW1p[i] = pack2(W1[(2 * p) * 64 + k], W1[(2 * p + 1) * 64 + k]);
    }
    for (int i = t; i < 12288; i += 256) {
        int k = i / 96, j = i % 96, c = j >> 5, p = j & 31;
        // output neuron o = 3f + c ; pair p covers f=2p, 2p+1
        sW2p[i] = pack2(W2[(6 * p + c) * 128 + k], W2[(6 * p + 3 + c) * 128 + k]);
    }
    if (t < 32) sB0p[t] = pack2(b0[2 * t], b0[2 * t + 1]);
    if (t < 64) sB1p[t] = pack2(b1[2 * t], b1[2 * t + 1]);
    if (t < 96) {
        int c = t >> 5, p = t & 31;
        sB2p[t] = pack2(b2[6 * p + c], b2[6 * p + 3 + c]);
    }
    __syncthreads();

    int wid = t >> 5, lane = t & 31;
    float* stg = sStage + wid * 2080;

    for (int w = blockIdx.x * 8 + wid; w < N_EDGES / 32; w += gridDim.x * 8) {
        // stage this warp's 32x32 rf tile (coalesced)
        for (int i = lane; i < 1024; i += 32) {
            int r = i >> 5, c2 = i & 31;
            stg[r * 33 + c2] = rf[w * 1024 + i];
        }
        __syncwarp();
        int e = w * 32 + lane;
        float d = dij[e];
        float C = (d < 1.0f) ? (0.5f * (cospif(d) + 1.0f)) : 0.0f;

        ull h0[32];
        {
            ull a0[32];
#pragma unroll
            for (int p = 0; p < 32; p++) a0[p] = sB0p[p];
#pragma unroll 4
            for (int k = 0; k < 32; k++) {
                float h = stg[lane * 33 + k];
                ull hp = pack2(h, h);
                const ull* wr = sW0p + k * 32;
#pragma unroll
                for (int p = 0; p < 32; p++) a0[p] = fma2(wr[p], hp, a0[p]);
            }
#pragma unroll
            for (int p = 0; p < 32; p++) {
                float x, y; unpack2(a0[p], x, y);
                h0[p] = pack2(siluf(x), siluf(y));
            }
        }
        __syncwarp();   // rf staging no longer needed

        ull h1[64];
        {
            ull a1[64];
#pragma unroll
            for (int p = 0; p < 64; p++) a1[p] = sB1p[p];
#pragma unroll 2
            for (int p0 = 0; p0 < 32; p0++) {
                float hx, hy; unpack2(h0[p0], hx, hy);
                ull hpx = pack2(hx, hx), hpy = pack2(hy, hy);
                const ull* wrx = sW1p + (2 * p0) * 64;
                const ull* wry = wrx + 64;
#pragma unroll
                for (int p = 0; p < 64; p++) a1[p] = fma2(wrx[p], hpx, a1[p]);
#pragma unroll
                for (int p = 0; p < 64; p++) a1[p] = fma2(wry[p], hpy, a1[p]);
            }
#pragma unroll
            for (int p = 0; p < 64; p++) {
                float x, y; unpack2(a1[p], x, y);
                h1[p] = pack2(siluf(x), siluf(y));
            }
        }

        int ebase = w * 32;
        for (int c = 0; c < 3; c++) {
            ull a2[32];
#pragma unroll
            for (int p = 0; p < 32; p++) a2[p] = sB2p[c * 32 + p];
#pragma unroll 2
            for (int p0 = 0; p0 < 64; p0++) {
                float hx, hy; unpack2(h1[p0], hx, hy);
                ull hpx = pack2(hx, hx), hpy = pack2(hy, hy);
                const ull* wrx = sW2p + (2 * p0) * 96 + c * 32;
                const ull* wry = wrx + 96;
#pragma unroll
                for (int p = 0; p < 32; p++) a2[p] = fma2(wrx[p], hpx, a2[p]);
#pragma unroll
                for (int p = 0; p < 32; p++) a2[p] = fma2(wry[p], hpy, a2[p]);
            }
#pragma unroll
            for (int p = 0; p < 32; p++) {
                float x, y; unpack2(a2[p], x, y);
                stg[lane * 65 + 2 * p]     = siluf(x) * C;
                stg[lane * 65 + 2 * p + 1] = siluf(y) * C;
            }
            __syncwarp();
            for (int e2 = 0; e2 < 32; e2++) {
                float2 v = make_float2(stg[e2 * 65 + 2 * lane], stg[e2 * 65 + 2 * lane + 1]);
                *(float2*)(g_rfv + (ebase + e2) * 192 + c * 64 + 2 * lane) = v;
            }
            __syncwarp();
        }
    }
}

// ============== K3: dst-centric segment reduction (warp per atom) ==============
__global__ void k_reduce(const int* __restrict__ pr) {
    int lane = threadIdx.x & 31;
    int wid = threadIdx.x >> 5;
    for (int n = blockIdx.x * (blockDim.x >> 5) + wid; n < N_ATOMS;
         n += gridDim.x * (blockDim.x >> 5)) {
        float2 acc[9];
#pragma unroll
        for (int c = 0; c < 9; c++) acc[c] = make_float2(0.f, 0.f);
        int beg = g_off[n], end = g_off[n + 1];
        for (int j = beg; j < end; j++) {
            int e = g_slot[j];
            int s = pr[N_EDGES + e];                // src = row 1
            const float2* rp = (const float2*)(g_rfv + e * 192);
            float2 r0 = rp[lane];
            float2 r1 = rp[32 + lane];
            float2 r2 = rp[64 + lane];
            const float2* cp = (const float2*)(g_comps + s * 576);
#pragma unroll
            for (int c = 0; c < 9; c++) {
                float2 v = cp[c * 32 + lane];
                float2 sc = (c == 0) ? r0 : (c < 4) ? r1 : r2;
                acc[c].x += sc.x * v.x;
                acc[c].y += sc.y * v.y;
            }
        }
        float2* mp = (float2*)(g_msg + n * 576);
#pragma unroll
        for (int c = 0; c < 9; c++) mp[c * 32 + lane] = acc[c];
    }
}

// ============== K4: O(3) product, decompose, normalize, linears, update ==============
__global__ void k_node_post(const float* __restrict__ X, const float* __restrict__ chg,
                            const float* __restrict__ Wt, float* __restrict__ out) {
    extern __shared__ float sm[];
    float* sWT = sm;             // 12288: Wt[3..5] transposed [m][f][g]
    float* sXn = sm + 12288;     // 576: normalized X  [f][9]
    float* sD  = sXn + 576;      // 576: normalized qP comps [c][f]
    float* sDX = sD + 576;       // 576: dX comps [c][g]
    float* sM  = sDX + 576;      // 576
    float* sY  = sM + 576;       // 576
    int t = threadIdx.x;
    for (int i = t; i < 12288; i += blockDim.x) {
        int m = i >> 12, r = i & 4095, f = r >> 6, g = r & 63;
        sWT[i] = Wt[(3 + m) * 4096 + g * 64 + f];
    }
    __syncthreads();
    for (int n = blockIdx.x; n < N_ATOMS; n += gridDim.x) {
        for (int i = t; i < 576; i += blockDim.x) {
            sXn[i] = X[n * 576 + i];
            sM[i]  = g_msg[n * 576 + i];
            sY[i]  = g_comps[n * 576 + i];
        }
        __syncthreads();
        float q = 1.0f + 0.1f * chg[n];
        if (t < 64) {
            int f = t;
            float xv[9]; float tn = 0.f;
#pragma unroll
            for (int j = 0; j < 9; j++) { float v = sXn[f * 9 + j]; xv[j] = v; tn += v * v; }
            float inv = 1.f / (tn + 1.f);
#pragma unroll
            for (int j = 0; j < 9; j++) { xv[j] *= inv; sXn[f * 9 + j] = xv[j]; }
            float cm[9], cy[9];
#pragma unroll
            for (int j = 0; j < 9; j++) { cm[j] = sM[j * 64 + f]; cy[j] = sY[j * 64 + f]; }
            float M[9], Y[9];
            recon(cm, M); recon(cy, Y);
            float P[9];
#pragma unroll
            for (int j = 0; j < 9; j++) P[j] = 0.f;
            madd3(M, Y, P);
            madd3(Y, M, P);
            float tn2 = 0.f;
#pragma unroll
            for (int j = 0; j < 9; j++) { P[j] *= q; tn2 += P[j] * P[j]; }
            float invn = 1.f / (tn2 + 1.f);
            float c[9]; decomp(P, c);
#pragma unroll
            for (int j = 0; j < 9; j++) sD[j * 64 + f] = c[j] * invn;
        }
        __syncthreads();
        for (int i = t; i < 576; i += blockDim.x) {
            int c = i >> 6, g = i & 63;
            int m = (c == 0) ? 0 : (c < 4) ? 1 : 2;
            const float* wr = sWT + m * 4096;
            const float* in = sD + c * 64;
            float acc = 0.f;
#pragma unroll 8
            for (int f = 0; f < 64; f++) acc += wr[f * 64 + g] * in[f];
            sDX[i] = acc;
        }
        __syncthreads();
        if (t < 64) {
            int g = t;
            float cd[9];
#pragma unroll
            for (int j = 0; j < 9; j++) cd[j] = sDX[j * 64 + g];
            float dx[9];
            recon(cd, dx);
            float dd[9];
#pragma unroll
            for (int j = 0; j < 9; j++) dd[j] = 0.f;
            madd3(dx, dx, dd);
#pragma unroll
            for (int j = 0; j < 9; j++)
                out[n * 576 + g * 9 + j] = sXn[g * 9 + j] + dx[j] + q * dd[j];
        }
        __syncthreads();
    }
}

// ---------------- launch ----------------
extern "C" void kernel_launch(void* const* d_in, const int* in_sizes, int n_in,
                              void* d_out, int out_size) {
    const float* X   = (const float*)d_in[0];
    const int*   pr  = (const int*)d_in[1];
    const float* dij = (const float*)d_in[2];
    const float* rf  = (const float*)d_in[3];
    const float* chg = (const float*)d_in[4];
    const float* W0  = (const float*)d_in[5];
    const float* b0  = (const float*)d_in[6];
    const float* W1  = (const float*)d_in[7];
    const float* b1  = (const float*)d_in[8];
    const float* W2  = (const float*)d_in[9];
    const float* b2  = (const float*)d_in[10];
    const float* Wt  = (const float*)d_in[11];
    float* out = (float*)d_out;

    cudaFuncSetAttribute(k_edge_mlp, cudaFuncAttributeMaxDynamicSharedMemorySize, 207360);
    cudaFuncSetAttribute(k_node_pre, cudaFuncAttributeMaxDynamicSharedMemorySize, 53760);
    cudaFuncSetAttribute(k_node_post, cudaFuncAttributeMaxDynamicSharedMemorySize, 60672);

    k_zero<<<(N_ATOMS + 255) / 256, 256>>>();
    k_hist<<<(N_EDGES + 255) / 256, 256>>>(pr);
    k_scan<<<1, 1024>>>();
    k_scatter<<<(N_EDGES + 255) / 256, 256>>>(pr);
    k_node_pre<<<592, 192, 53760>>>(X, Wt);
    k_edge_mlp<<<148, 256, 207360>>>(rf, dij, W0, b0, W1, b1, W2, b2);
    k_reduce<<<2500, 256>>>(pr);
    k_node_post<<<592, 192, 60672>>>(X, chg, Wt, out);
}